// round 16
// baseline (speedup 1.0000x reference)
#include <cuda_runtime.h>
#include <cuda_bf16.h>

#define NMAX 100000
#define DH   64
#define GMAX 64
#define DOUT 32
#define BMAX 65   // <= 64 thresholds -> <= 65 buckets
#define BBLK 8    // buckets per k_thresh block

// ---- scratch (__device__ globals; no allocation allowed) -------------------
__device__ __align__(256) float2 d_pq[(size_t)BMAX * NMAX];  // (p,q), layout [b][i]
__device__ __align__(256) float4 d_ninfo[NMAX];              // (a=dinv*c, dinv, bits(b), 0)
__device__ float d_S[NMAX];          // S, then reused as c
__device__ float d_dinv[NMAX];
__device__ int   d_deg[NMAX];
__device__ float d_u[BMAX * DH];     // (v .* mask_b) @ W2
__device__ float d_w[BMAX * DH];     // (b1 .* mask_b) @ W2
__device__ float d_tsort[DH];
__device__ int   d_Beff;
__device__ unsigned d_cminb, d_cmaxb;
__device__ int   d_gstart[GMAX + 2];
__device__ float d_pooled[GMAX * DH];

// 1) in-degree on dst (4 edges/thread, int4 loads); ALSO zeroes d_S/d_pooled
//    and seeds min/max (all consumed strictly after this kernel completes).
__global__ __launch_bounds__(256) void k_deg(const int* __restrict__ ei, int E, int N) {
    int t = blockIdx.x * blockDim.x + threadIdx.x;
    if (t < N) d_S[t] = 0.f;
    if (t < GMAX * DH) d_pooled[t] = 0.f;
    if (t == 0) { d_cminb = 0x7f800000u; d_cmaxb = 0u; }
    int e = t * 4;
    if (e + 3 < E) {
        int4 d4 = *(const int4*)&ei[E + e];
        atomicAdd(&d_deg[d4.x], 1);
        atomicAdd(&d_deg[d4.y], 1);
        atomicAdd(&d_deg[d4.z], 1);
        atomicAdd(&d_deg[d4.w], 1);
    } else {
        for (int k = e; k < E; k++) atomicAdd(&d_deg[ei[E + k]], 1);
    }
}

// 2) S[dst] += rsqrt(deg[src]+1)
__global__ void k_S(const int* __restrict__ ei, int E) {
    int e = blockIdx.x * blockDim.x + threadIdx.x;
    if (e < E) {
        float ds = rsqrtf((float)d_deg[ei[e]] + 1.0f);
        atomicAdd(&d_S[ei[E + e]], ds);
    }
}

// 3) per node: dinv, c = dinv*(S+dinv); global min/max of c
__global__ __launch_bounds__(256) void k_c(int N) {
    int i = blockIdx.x * blockDim.x + threadIdx.x;
    bool valid = (i < N);
    float dv = 0.f, c = 0.f;
    if (valid) {
        dv = rsqrtf((float)d_deg[i] + 1.0f);
        c  = dv * (d_S[i] + dv);
    }
    unsigned cb = __float_as_uint(c);              // c > 0 -> bits order == float order
    unsigned mn = __reduce_min_sync(0xffffffffu, valid ? cb : 0x7f800000u);
    unsigned mx = __reduce_max_sync(0xffffffffu, valid ? cb : 0u);
    if ((threadIdx.x & 31) == 0) {
        atomicMin(&d_cminb, mn);
        atomicMax(&d_cmaxb, mx);
    }
    if (valid) { d_dinv[i] = dv; d_S[i] = c; }     // reuse S slot as c
}

// 4) PARALLEL table build: block k owns buckets [k*BBLK, k*BBLK+BBLK).
__global__ __launch_bounds__(256) void k_thresh(const float* __restrict__ emb,
                                                const float* __restrict__ W1,
                                                const float* __restrict__ b1,
                                                const float* __restrict__ W2) {
    __shared__ float sW2[DH * DH];                 // 16 KB
    __shared__ float sv[DH], sb1[DH], st[DH], ssort[DH];
    __shared__ int   sinr[DH], sdim[DH], scnt;
    int t = threadIdx.x;
    for (int k = t; k < DH * DH / 4; k += 256)
        ((float4*)sW2)[k] = ((const float4*)W2)[k];
    if (t < DH) {
        float a = 0.f;
        #pragma unroll
        for (int k = 0; k < DH; k++) a = fmaf(emb[k], W1[k * DH + t], a);
        sv[t] = a; sb1[t] = b1[t];
    }
    __syncthreads();
    float cmin = __uint_as_float(d_cminb);
    float cmax = __uint_as_float(d_cmaxb);
    if (t < DH) {
        float vv = sv[t];
        float th = -sb1[t] / vv;                   // NaN/inf auto-fail range test
        int inr = (vv != 0.f) && (th > cmin) && (th < cmax);
        st[t] = th; sinr[t] = inr;
    }
    __syncthreads();
    if (t < DH && sinr[t]) {
        float th = st[t]; int r = 0;
        for (int d = 0; d < DH; d++)
            if (sinr[d] && (st[d] < th || (st[d] == th && d < t))) r++;
        ssort[r] = th;
        sdim[r]  = t;                              // which dim flips at rank r
    }
    if (t == 0) {
        int c = 0;
        for (int d = 0; d < DH; d++) c += sinr[d];
        scnt = c;
        if (blockIdx.x == 0) d_Beff = c + 1;
    }
    __syncthreads();
    int cnt = scnt;
    if (blockIdx.x == 0 && t < cnt) d_tsort[t] = ssort[t];

    int b0 = blockIdx.x * BBLK;
    if (b0 > cnt) return;                          // buckets 0..cnt exist
    int bend = min(b0 + BBLK, cnt + 1);
    if (t < DH) {
        int j = t;
        float lo = (b0 == 0)   ? cmin : ssort[b0 - 1];
        float hi = (b0 == cnt) ? cmax : ssort[b0];
        float rep = 0.5f * (lo + hi);
        float uu = 0.f, ww = 0.f;
        #pragma unroll 8
        for (int d = 0; d < DH; d++) {
            if (fmaf(rep, sv[d], sb1[d]) > 0.f) {
                float wdj = sW2[d * DH + j];
                uu = fmaf(sv[d],  wdj, uu);
                ww = fmaf(sb1[d], wdj, ww);
            }
        }
        d_u[b0 * DH + j] = uu;
        d_w[b0 * DH + j] = ww;
        for (int b = b0 + 1; b < bend; b++) {      // crossing th flips one dim
            int dk = sdim[b - 1];
            float vv = sv[dk], bb = sb1[dk];
            float wdj = sW2[dk * DH + j];
            float s = (vv > 0.f) ? 1.f : -1.f;
            uu = fmaf(s * vv, wdj, uu);
            ww = fmaf(s * bb, wdj, ww);
            d_u[b * DH + j] = uu;
            d_w[b * DH + j] = ww;
        }
    }
}

// 5) per node: bucket id, ninfo; graph bounds; zero pq rows [0,Beff) (fused)
__global__ __launch_bounds__(256) void k_bucket(const int* __restrict__ batch,
                                                int N, int G) {
    __shared__ float ts[DH];
    __shared__ int sBeff;
    if (threadIdx.x == 0) sBeff = d_Beff;
    if (threadIdx.x < DH) ts[threadIdx.x] = d_tsort[threadIdx.x];
    __syncthreads();
    int i = blockIdx.x * blockDim.x + threadIdx.x;
    int Beff = sBeff;
    int cnt = Beff - 1;
    if (i < N) {
        float c = d_S[i];
        float dv = d_dinv[i];
        int b = 0;
        for (int k = 0; k < cnt; k++) b += (ts[k] < c);
        d_ninfo[i] = make_float4(dv * c, dv, __int_as_float(b), 0.f);
        float2 z = make_float2(0.f, 0.f);
        for (int b2 = 0; b2 < Beff; b2++)
            d_pq[(size_t)b2 * N + i] = z;          // coalesced per-row
    }
    if (i <= N) {
        int cur  = (i < N) ? batch[i] : G;
        int prev = (i == 0) ? -1 : batch[i - 1];
        for (int g = prev + 1; g <= cur; g++) d_gstart[g] = i;
    }
}

// 7) edge aggregation: 8-byte float2 RED per edge (1 edge/thread — measured best)
__global__ __launch_bounds__(256) void k_edge(const int* __restrict__ ei, int E, int N) {
    int e = blockIdx.x * blockDim.x + threadIdx.x;
    if (e >= E) return;
    int s = ei[e];
    int d = ei[E + e];
    float4 ni = d_ninfo[s];
    int b = __float_as_int(ni.z);
    atomicAdd(&d_pq[(size_t)b * N + d], make_float2(ni.x, ni.y));
}

// 8) per node: h2 = relu(dinv*(self + sum_b p*u_b+q*w_b) + b2); fused mean-pool
__global__ __launch_bounds__(256) void k_out(const int* __restrict__ batch,
                                             const float* __restrict__ b2, int N) {
    __shared__ float su[BMAX * DH];
    __shared__ float sw[BMAX * DH];
    __shared__ float swarp[8][DH];
    __shared__ float sb2[DH];
    __shared__ int sg0;
    int t = threadIdx.x;
    int Beff = d_Beff;
    for (int k = t; k < Beff * DH; k += 256) { su[k] = d_u[k]; sw[k] = d_w[k]; }
    if (t < DH) sb2[t] = b2[t];
    int i0 = blockIdx.x * 64;
    if (t == 0) sg0 = batch[i0];
    __syncthreads();

    int node = i0 + (t >> 2);
    int part = t & 3;
    int g0 = sg0;

    float acc[16];
    #pragma unroll
    for (int k = 0; k < 16; k++) acc[k] = 0.f;
    float dv = 0.f;
    int g = g0;
    if (node < N) {
        float4 ni = d_ninfo[node];
        dv = ni.y;
        g = batch[node];
        {   // self-loop term seeds acc
            int bi = __float_as_int(ni.z);
            const float4* u4 = (const float4*)&su[bi * DH + part * 16];
            const float4* w4 = (const float4*)&sw[bi * DH + part * 16];
            #pragma unroll
            for (int jj = 0; jj < 4; jj++) {
                float4 u = u4[jj], w = w4[jj];
                acc[jj * 4 + 0] = fmaf(ni.x, u.x, dv * w.x);
                acc[jj * 4 + 1] = fmaf(ni.x, u.y, dv * w.y);
                acc[jj * 4 + 2] = fmaf(ni.x, u.z, dv * w.z);
                acc[jj * 4 + 3] = fmaf(ni.x, u.w, dv * w.w);
            }
        }
        for (int b = 0; b < Beff; b++) {
            float2 pq = d_pq[(size_t)b * N + node];
            if (pq.y != 0.f) {
                const float4* u4 = (const float4*)&su[b * DH + part * 16];
                const float4* w4 = (const float4*)&sw[b * DH + part * 16];
                #pragma unroll
                for (int jj = 0; jj < 4; jj++) {
                    float4 u = u4[jj], w = w4[jj];
                    acc[jj * 4 + 0] = fmaf(pq.x, u.x, fmaf(pq.y, w.x, acc[jj * 4 + 0]));
                    acc[jj * 4 + 1] = fmaf(pq.x, u.y, fmaf(pq.y, w.y, acc[jj * 4 + 1]));
                    acc[jj * 4 + 2] = fmaf(pq.x, u.z, fmaf(pq.y, w.z, acc[jj * 4 + 2]));
                    acc[jj * 4 + 3] = fmaf(pq.x, u.w, fmaf(pq.y, w.w, acc[jj * 4 + 3]));
                }
            }
        }
    }
    float h[16];
    #pragma unroll
    for (int k = 0; k < 16; k++)
        h[k] = (node < N) ? fmaxf(fmaf(dv, acc[k], sb2[part * 16 + k]), 0.f) : 0.f;

    if (node < N && g != g0) {
        #pragma unroll
        for (int k = 0; k < 16; k++)
            atomicAdd(&d_pooled[g * DH + part * 16 + k], h[k]);
        #pragma unroll
        for (int k = 0; k < 16; k++) h[k] = 0.f;
    }
    #pragma unroll
    for (int k = 0; k < 16; k++) {
        h[k] += __shfl_xor_sync(0xffffffffu, h[k], 16);
        h[k] += __shfl_xor_sync(0xffffffffu, h[k], 8);
        h[k] += __shfl_xor_sync(0xffffffffu, h[k], 4);
    }
    int lane = t & 31, warp = t >> 5;
    if (lane < 4) {
        #pragma unroll
        for (int k = 0; k < 16; k++) swarp[warp][lane * 16 + k] = h[k];
    }
    __syncthreads();
    if (t < DH) {
        float tot = 0.f;
        #pragma unroll
        for (int wq = 0; wq < 8; wq++) tot += swarp[wq][t];
        atomicAdd(&d_pooled[g0 * DH + t], tot);
    }
}

// 9) per graph: mean + FC
__global__ __launch_bounds__(64) void k_pool(const float* __restrict__ fcW,
                                             const float* __restrict__ fcb,
                                             float* __restrict__ out) {
    int g = blockIdx.x;
    __shared__ float sp[DH];
    int t = threadIdx.x;
    int cnt = d_gstart[g + 1] - d_gstart[g];
    float inv = 1.f / fmaxf((float)cnt, 1.f);
    sp[t] = d_pooled[g * DH + t] * inv;
    __syncthreads();
    if (t < DOUT) {
        float r = fcb[t];
        #pragma unroll
        for (int f = 0; f < DH; f++) r = fmaf(sp[f], fcW[f * DOUT + t], r);
        out[g * DOUT + t] = r;
    }
}

extern "C" void kernel_launch(void* const* d_in, const int* in_sizes, int n_in,
                              void* d_out, int out_size) {
    // metadata order: x, edge_index, batch, emb, W1, b1, W2, b2, fcW, fcb
    const int*   ei    = (const int*)d_in[1];
    const int*   batch = (const int*)d_in[2];
    const float* emb   = (const float*)d_in[3];
    const float* W1    = (const float*)d_in[4];
    const float* b1    = (const float*)d_in[5];
    const float* W2    = (const float*)d_in[6];
    const float* b2    = (const float*)d_in[7];
    const float* fcW   = (const float*)d_in[8];
    const float* fcb   = (const float*)d_in[9];
    float* out = (float*)d_out;

    int N = in_sizes[0];
    int E = in_sizes[1] / 2;
    int G = out_size / DOUT;

    // zero d_deg via DMA (only buffer that must be zero before k_deg's atomics)
    void* p_deg;
    cudaGetSymbolAddress(&p_deg, d_deg);
    cudaMemsetAsync(p_deg, 0, (size_t)N * sizeof(int));

    const int tb = 256;
    k_deg<<<((E + 3) / 4 + tb - 1) / tb, tb>>>(ei, E, N);
    k_S<<<(E + tb - 1) / tb, tb>>>(ei, E);
    k_c<<<(N + tb - 1) / tb, tb>>>(N);
    k_thresh<<<(BMAX + BBLK - 1) / BBLK, tb>>>(emb, W1, b1, W2);
    k_bucket<<<(N + 1 + tb - 1) / tb, tb>>>(batch, N, G);
    k_edge<<<(E + tb - 1) / tb, tb>>>(ei, E, N);
    k_out<<<(N + 63) / 64, tb>>>(batch, b2, N);
    k_pool<<<G, 64>>>(fcW, fcb, out);
}

// round 17
// speedup vs baseline: 1.0672x; 1.0672x over previous
#include <cuda_runtime.h>
#include <cuda_bf16.h>

#define NMAX 100000
#define DH   64
#define GMAX 64
#define DOUT 32
#define BMAX 65   // <= 64 thresholds -> <= 65 buckets
#define BBLK 8    // buckets per k_thresh block

// PDL: wait for predecessor grid's writes / signal dependent grid may launch
#define GRID_WAIT()    asm volatile("griddepcontrol.wait;" ::: "memory")
#define GRID_TRIGGER() asm volatile("griddepcontrol.launch_dependents;")

// ---- scratch (__device__ globals; no allocation allowed) -------------------
__device__ __align__(256) float2 d_pq[(size_t)BMAX * NMAX];  // (p,q), layout [b][i]
__device__ __align__(256) float4 d_ninfo[NMAX];              // (a=dinv*c, dinv, bits(b), 0)
__device__ float d_S[NMAX];          // S, then reused as c
__device__ float d_dinv[NMAX];
__device__ int   d_deg[NMAX];
__device__ float d_u[BMAX * DH];     // (v .* mask_b) @ W2
__device__ float d_w[BMAX * DH];     // (b1 .* mask_b) @ W2
__device__ float d_tsort[DH];
__device__ int   d_Beff;
__device__ unsigned d_cminb, d_cmaxb;
__device__ int   d_gstart[GMAX + 2];
__device__ float d_pooled[GMAX * DH];

// 0) zero deg, S, pooled, min/max
__global__ __launch_bounds__(256) void k_init(int N) {
    int i = blockIdx.x * blockDim.x + threadIdx.x;
    if (i < N) { d_deg[i] = 0; d_S[i] = 0.f; }
    if (i < GMAX * DH) d_pooled[i] = 0.f;
    if (i == 0) { d_cminb = 0x7f800000u; d_cmaxb = 0u; }
    GRID_TRIGGER();
}

// 1) in-degree on dst (4 edges/thread, int4 loads)
__global__ __launch_bounds__(256) void k_deg(const int* __restrict__ ei, int E) {
    int t = blockIdx.x * blockDim.x + threadIdx.x;
    int e = t * 4;
    GRID_WAIT();                                    // d_deg must be zeroed
    if (e + 3 < E) {
        int4 d4 = *(const int4*)&ei[E + e];
        atomicAdd(&d_deg[d4.x], 1);
        atomicAdd(&d_deg[d4.y], 1);
        atomicAdd(&d_deg[d4.z], 1);
        atomicAdd(&d_deg[d4.w], 1);
    } else {
        for (int k = e; k < E; k++) atomicAdd(&d_deg[ei[E + k]], 1);
    }
    GRID_TRIGGER();
}

// 2) S[dst] += rsqrt(deg[src]+1)
__global__ void k_S(const int* __restrict__ ei, int E) {
    int e = blockIdx.x * blockDim.x + threadIdx.x;
    GRID_WAIT();                                    // d_deg final
    if (e < E) {
        float ds = rsqrtf((float)d_deg[ei[e]] + 1.0f);
        atomicAdd(&d_S[ei[E + e]], ds);
    }
    GRID_TRIGGER();
}

// 3) per node: dinv, c = dinv*(S+dinv); global min/max of c
__global__ __launch_bounds__(256) void k_c(int N) {
    int i = blockIdx.x * blockDim.x + threadIdx.x;
    bool valid = (i < N);
    GRID_WAIT();                                    // d_S final
    float dv = 0.f, c = 0.f;
    if (valid) {
        dv = rsqrtf((float)d_deg[i] + 1.0f);
        c  = dv * (d_S[i] + dv);
    }
    unsigned cb = __float_as_uint(c);              // c > 0 -> bits order == float order
    unsigned mn = __reduce_min_sync(0xffffffffu, valid ? cb : 0x7f800000u);
    unsigned mx = __reduce_max_sync(0xffffffffu, valid ? cb : 0u);
    if ((threadIdx.x & 31) == 0) {
        atomicMin(&d_cminb, mn);
        atomicMax(&d_cmaxb, mx);
    }
    if (valid) { d_dinv[i] = dv; d_S[i] = c; }     // reuse S slot as c
    GRID_TRIGGER();
}

// 4) PARALLEL table build: block k owns buckets [k*BBLK, k*BBLK+BBLK).
//    W2 staging + v dot run BEFORE the PDL wait (stable harness inputs).
__global__ __launch_bounds__(256) void k_thresh(const float* __restrict__ emb,
                                                const float* __restrict__ W1,
                                                const float* __restrict__ b1,
                                                const float* __restrict__ W2) {
    __shared__ float sW2[DH * DH];                 // 16 KB
    __shared__ float sv[DH], sb1[DH], st[DH], ssort[DH];
    __shared__ int   sinr[DH], sdim[DH], scnt;
    int t = threadIdx.x;
    for (int k = t; k < DH * DH / 4; k += 256)
        ((float4*)sW2)[k] = ((const float4*)W2)[k];
    if (t < DH) {
        float a = 0.f;
        #pragma unroll
        for (int k = 0; k < DH; k++) a = fmaf(emb[k], W1[k * DH + t], a);
        sv[t] = a; sb1[t] = b1[t];
    }
    __syncthreads();
    GRID_WAIT();                                    // d_cminb/d_cmaxb final
    float cmin = __uint_as_float(d_cminb);
    float cmax = __uint_as_float(d_cmaxb);
    if (t < DH) {
        float vv = sv[t];
        float th = -sb1[t] / vv;                   // NaN/inf auto-fail range test
        int inr = (vv != 0.f) && (th > cmin) && (th < cmax);
        st[t] = th; sinr[t] = inr;
    }
    __syncthreads();
    if (t < DH && sinr[t]) {
        float th = st[t]; int r = 0;
        for (int d = 0; d < DH; d++)
            if (sinr[d] && (st[d] < th || (st[d] == th && d < t))) r++;
        ssort[r] = th;
        sdim[r]  = t;                              // which dim flips at rank r
    }
    if (t == 0) {
        int c = 0;
        for (int d = 0; d < DH; d++) c += sinr[d];
        scnt = c;
        if (blockIdx.x == 0) d_Beff = c + 1;
    }
    __syncthreads();
    int cnt = scnt;
    if (blockIdx.x == 0 && t < cnt) d_tsort[t] = ssort[t];

    int b0 = blockIdx.x * BBLK;
    if (b0 <= cnt) {                               // buckets 0..cnt exist
        int bend = min(b0 + BBLK, cnt + 1);
        if (t < DH) {
            int j = t;
            float lo = (b0 == 0)   ? cmin : ssort[b0 - 1];
            float hi = (b0 == cnt) ? cmax : ssort[b0];
            float rep = 0.5f * (lo + hi);
            float uu = 0.f, ww = 0.f;
            #pragma unroll 8
            for (int d = 0; d < DH; d++) {
                if (fmaf(rep, sv[d], sb1[d]) > 0.f) {
                    float wdj = sW2[d * DH + j];
                    uu = fmaf(sv[d],  wdj, uu);
                    ww = fmaf(sb1[d], wdj, ww);
                }
            }
            d_u[b0 * DH + j] = uu;
            d_w[b0 * DH + j] = ww;
            for (int b = b0 + 1; b < bend; b++) {  // crossing th flips one dim
                int dk = sdim[b - 1];
                float vv = sv[dk], bb = sb1[dk];
                float wdj = sW2[dk * DH + j];
                float s = (vv > 0.f) ? 1.f : -1.f;
                uu = fmaf(s * vv, wdj, uu);
                ww = fmaf(s * bb, wdj, ww);
                d_u[b * DH + j] = uu;
                d_w[b * DH + j] = ww;
            }
        }
    }
    GRID_TRIGGER();
}

// 5) per node: bucket id, ninfo; graph bounds; zero pq rows [0,Beff) (fused)
//    gstart scan (stable batch input) runs BEFORE the PDL wait.
__global__ __launch_bounds__(256) void k_bucket(const int* __restrict__ batch,
                                                int N, int G) {
    __shared__ float ts[DH];
    __shared__ int sBeff;
    int i = blockIdx.x * blockDim.x + threadIdx.x;
    if (i <= N) {
        int cur  = (i < N) ? batch[i] : G;
        int prev = (i == 0) ? -1 : batch[i - 1];
        for (int g = prev + 1; g <= cur; g++) d_gstart[g] = i;
    }
    GRID_WAIT();                                    // d_tsort/d_Beff/c final
    if (threadIdx.x == 0) sBeff = d_Beff;
    if (threadIdx.x < DH) ts[threadIdx.x] = d_tsort[threadIdx.x];
    __syncthreads();
    int Beff = sBeff;
    int cnt = Beff - 1;
    if (i < N) {
        float c = d_S[i];
        float dv = d_dinv[i];
        int b = 0;
        for (int k = 0; k < cnt; k++) b += (ts[k] < c);
        d_ninfo[i] = make_float4(dv * c, dv, __int_as_float(b), 0.f);
        float2 z = make_float2(0.f, 0.f);
        for (int b2 = 0; b2 < Beff; b2++)
            d_pq[(size_t)b2 * N + i] = z;          // coalesced per-row
    }
    GRID_TRIGGER();
}

// 7) edge aggregation: 8-byte float2 RED per edge (1 edge/thread — measured best)
__global__ __launch_bounds__(256) void k_edge(const int* __restrict__ ei, int E, int N) {
    int e = blockIdx.x * blockDim.x + threadIdx.x;
    GRID_WAIT();                                    // ninfo + pq zero final
    if (e < E) {
        int s = ei[e];
        int d = ei[E + e];
        float4 ni = d_ninfo[s];
        int b = __float_as_int(ni.z);
        atomicAdd(&d_pq[(size_t)b * N + d], make_float2(ni.x, ni.y));
    }
    GRID_TRIGGER();
}

// 8) per node: h2 = relu(dinv*(self + sum_b p*u_b+q*w_b) + b2); fused mean-pool
__global__ __launch_bounds__(256) void k_out(const int* __restrict__ batch,
                                             const float* __restrict__ b2, int N) {
    __shared__ float su[BMAX * DH];
    __shared__ float sw[BMAX * DH];
    __shared__ float swarp[8][DH];
    __shared__ float sb2[DH];
    __shared__ int sg0;
    int t = threadIdx.x;
    if (t < DH) sb2[t] = b2[t];                    // stable input, pre-wait
    int i0 = blockIdx.x * 64;
    if (t == 0) sg0 = batch[i0];
    GRID_WAIT();                                    // pq sums final
    int Beff = d_Beff;
    for (int k = t; k < Beff * DH; k += 256) { su[k] = d_u[k]; sw[k] = d_w[k]; }
    __syncthreads();

    int node = i0 + (t >> 2);
    int part = t & 3;
    int g0 = sg0;

    float acc[16];
    #pragma unroll
    for (int k = 0; k < 16; k++) acc[k] = 0.f;
    float dv = 0.f;
    int g = g0;
    if (node < N) {
        float4 ni = d_ninfo[node];
        dv = ni.y;
        g = batch[node];
        {   // self-loop term seeds acc
            int bi = __float_as_int(ni.z);
            const float4* u4 = (const float4*)&su[bi * DH + part * 16];
            const float4* w4 = (const float4*)&sw[bi * DH + part * 16];
            #pragma unroll
            for (int jj = 0; jj < 4; jj++) {
                float4 u = u4[jj], w = w4[jj];
                acc[jj * 4 + 0] = fmaf(ni.x, u.x, dv * w.x);
                acc[jj * 4 + 1] = fmaf(ni.x, u.y, dv * w.y);
                acc[jj * 4 + 2] = fmaf(ni.x, u.z, dv * w.z);
                acc[jj * 4 + 3] = fmaf(ni.x, u.w, dv * w.w);
            }
        }
        for (int b = 0; b < Beff; b++) {
            float2 pq = d_pq[(size_t)b * N + node];
            if (pq.y != 0.f) {
                const float4* u4 = (const float4*)&su[b * DH + part * 16];
                const float4* w4 = (const float4*)&sw[b * DH + part * 16];
                #pragma unroll
                for (int jj = 0; jj < 4; jj++) {
                    float4 u = u4[jj], w = w4[jj];
                    acc[jj * 4 + 0] = fmaf(pq.x, u.x, fmaf(pq.y, w.x, acc[jj * 4 + 0]));
                    acc[jj * 4 + 1] = fmaf(pq.x, u.y, fmaf(pq.y, w.y, acc[jj * 4 + 1]));
                    acc[jj * 4 + 2] = fmaf(pq.x, u.z, fmaf(pq.y, w.z, acc[jj * 4 + 2]));
                    acc[jj * 4 + 3] = fmaf(pq.x, u.w, fmaf(pq.y, w.w, acc[jj * 4 + 3]));
                }
            }
        }
    }
    float h[16];
    #pragma unroll
    for (int k = 0; k < 16; k++)
        h[k] = (node < N) ? fmaxf(fmaf(dv, acc[k], sb2[part * 16 + k]), 0.f) : 0.f;

    if (node < N && g != g0) {
        #pragma unroll
        for (int k = 0; k < 16; k++)
            atomicAdd(&d_pooled[g * DH + part * 16 + k], h[k]);
        #pragma unroll
        for (int k = 0; k < 16; k++) h[k] = 0.f;
    }
    #pragma unroll
    for (int k = 0; k < 16; k++) {
        h[k] += __shfl_xor_sync(0xffffffffu, h[k], 16);
        h[k] += __shfl_xor_sync(0xffffffffu, h[k], 8);
        h[k] += __shfl_xor_sync(0xffffffffu, h[k], 4);
    }
    int lane = t & 31, warp = t >> 5;
    if (lane < 4) {
        #pragma unroll
        for (int k = 0; k < 16; k++) swarp[warp][lane * 16 + k] = h[k];
    }
    __syncthreads();
    if (t < DH) {
        float tot = 0.f;
        #pragma unroll
        for (int wq = 0; wq < 8; wq++) tot += swarp[wq][t];
        atomicAdd(&d_pooled[g0 * DH + t], tot);
    }
    GRID_TRIGGER();
}

// 9) per graph: mean + FC
__global__ __launch_bounds__(64) void k_pool(const float* __restrict__ fcW,
                                             const float* __restrict__ fcb,
                                             float* __restrict__ out) {
    int g = blockIdx.x;
    __shared__ float sp[DH];
    int t = threadIdx.x;
    GRID_WAIT();                                    // d_pooled final
    int cnt = d_gstart[g + 1] - d_gstart[g];
    float inv = 1.f / fmaxf((float)cnt, 1.f);
    sp[t] = d_pooled[g * DH + t] * inv;
    __syncthreads();
    if (t < DOUT) {
        float r = fcb[t];
        #pragma unroll
        for (int f = 0; f < DH; f++) r = fmaf(sp[f], fcW[f * DOUT + t], r);
        out[g * DOUT + t] = r;
    }
}

template <typename... Args>
static void launch_pdl(void (*kern)(Args...), dim3 grid, dim3 block, Args... args) {
    cudaLaunchConfig_t cfg = {};
    cfg.gridDim = grid;
    cfg.blockDim = block;
    cudaLaunchAttribute attr[1];
    attr[0].id = cudaLaunchAttributeProgrammaticStreamSerialization;
    attr[0].val.programmaticStreamSerializationAllowed = 1;
    cfg.attrs = attr;
    cfg.numAttrs = 1;
    cudaLaunchKernelEx(&cfg, kern, args...);
}

extern "C" void kernel_launch(void* const* d_in, const int* in_sizes, int n_in,
                              void* d_out, int out_size) {
    // metadata order: x, edge_index, batch, emb, W1, b1, W2, b2, fcW, fcb
    const int*   ei    = (const int*)d_in[1];
    const int*   batch = (const int*)d_in[2];
    const float* emb   = (const float*)d_in[3];
    const float* W1    = (const float*)d_in[4];
    const float* b1    = (const float*)d_in[5];
    const float* W2    = (const float*)d_in[6];
    const float* b2    = (const float*)d_in[7];
    const float* fcW   = (const float*)d_in[8];
    const float* fcb   = (const float*)d_in[9];
    float* out = (float*)d_out;

    int N = in_sizes[0];
    int E = in_sizes[1] / 2;
    int G = out_size / DOUT;

    const int tb = 256;
    k_init<<<(N + tb - 1) / tb, tb>>>(N);
    launch_pdl(k_deg,    dim3(((E + 3) / 4 + tb - 1) / tb), dim3(tb), ei, E);
    launch_pdl(k_S,      dim3((E + tb - 1) / tb),           dim3(tb), ei, E);
    launch_pdl(k_c,      dim3((N + tb - 1) / tb),           dim3(tb), N);
    launch_pdl(k_thresh, dim3((BMAX + BBLK - 1) / BBLK),    dim3(tb), emb, W1, b1, W2);
    launch_pdl(k_bucket, dim3((N + 1 + tb - 1) / tb),       dim3(tb), batch, N, G);
    launch_pdl(k_edge,   dim3((E + tb - 1) / tb),           dim3(tb), ei, E, N);
    launch_pdl(k_out,    dim3((N + 63) / 64),               dim3(tb), batch, b2, N);
    launch_pdl(k_pool,   dim3(G),                           dim3(64), fcW, fcb, out);
}